// round 16
// baseline (speedup 1.0000x reference)
#include <cuda_runtime.h>

#define N_NODES 50000
#define N_EDGES 800000
#define DIM 64
#define NCHUNK 49            // ceil(50000/1024)
#define PAD 65               // smem row pitch (floats), conflict-free
#define NPB 64               // nodes per block
#define THR 1024             // threads per block (32 warps, 2 nodes/warp)

// Scratch (device globals — no allocation allowed). BSS zero-init at load.
__device__ int   g_deg[N_NODES];
__device__ int   g_row[N_NODES + 1];
__device__ int   g_cur[N_NODES];
__device__ int   g_col[N_EDGES];
__device__ float g_x1[N_NODES * DIM];
__device__ int   g_chain_val[NCHUNK];
__device__ int   g_chain_flag[NCHUNK];   // epoch counts, never reset

// ------------------------------------------------------------------ hist
__global__ void k_hist(const int* __restrict__ ei) {
    int t = blockIdx.x * blockDim.x + threadIdx.x;
    if (t < N_EDGES / 4) {
        int4 d = ((const int4*)(ei + N_EDGES))[t];
        atomicAdd(&g_deg[d.x], 1);
        atomicAdd(&g_deg[d.y], 1);
        atomicAdd(&g_deg[d.z], 1);
        atomicAdd(&g_deg[d.w], 1);
    }
}

// -------------------- chained exclusive scan (one kernel, 49 blocks) -----
__global__ void __launch_bounds__(1024) k_scan_chain() {
    __shared__ int wsum[32];
    __shared__ int s_base;
    int t = threadIdx.x, lane = t & 31, wid = t >> 5;
    int b = blockIdx.x;
    int i = b * 1024 + t;
    int v = 0;
    if (i < N_NODES) { v = g_deg[i]; g_deg[i] = 0; }
    int sc = v;
    #pragma unroll
    for (int off = 1; off < 32; off <<= 1) {
        int n = __shfl_up_sync(0xffffffffu, sc, off);
        if (lane >= off) sc += n;
    }
    if (lane == 31) wsum[wid] = sc;
    __syncthreads();
    if (wid == 0) {
        int w = wsum[lane];
        #pragma unroll
        for (int off = 1; off < 32; off <<= 1) {
            int n = __shfl_up_sync(0xffffffffu, w, off);
            if (lane >= off) w += n;
        }
        wsum[lane] = w;
    }
    __syncthreads();
    int wpre  = (wid > 0) ? wsum[wid - 1] : 0;
    int total = wsum[31];
    if (t == 0) {
        int E = g_chain_flag[b];
        int base = 0;
        if (b > 0) {
            while (atomicAdd(&g_chain_flag[b - 1], 0) <= E) {}
            __threadfence();
            base = g_chain_val[b - 1];
        }
        g_chain_val[b] = base + total;
        __threadfence();
        atomicExch(&g_chain_flag[b], E + 1);
        s_base = base;
    }
    __syncthreads();
    int ex = s_base + wpre + sc - v;
    if (i < N_NODES) { g_row[i] = ex; g_cur[i] = ex; }
    if (i == 0) g_row[N_NODES] = N_EDGES;
}

// --------------------------------------------------------------- scatter
__global__ void k_scatter(const int* __restrict__ ei) {
    int t = blockIdx.x * blockDim.x + threadIdx.x;
    if (t < N_EDGES / 4) {
        int4 s = ((const int4*)ei)[t];
        int4 d = ((const int4*)(ei + N_EDGES))[t];
        g_col[atomicAdd(&g_cur[d.x], 1)] = s.x;
        g_col[atomicAdd(&g_cur[d.y], 1)] = s.y;
        g_col[atomicAdd(&g_cur[d.z], 1)] = s.z;
        g_col[atomicAdd(&g_cur[d.w], 1)] = s.w;
    }
}

// ------------- fused layer: aggregation + GEMM + bias + relu --------------
// Block owns 64 nodes, 1024 threads = 32 warps (2 nodes per warp).
// smem 66KB -> 2 blocks/SM -> 64 warps/SM (100% occ), 2-node serial chain.
__global__ void __launch_bounds__(THR, 2) k_layer(const float* __restrict__ x,
                                                  const float* __restrict__ Wl,
                                                  const float* __restrict__ bl,
                                                  const float* __restrict__ Wr,
                                                  float* __restrict__ out) {
    extern __shared__ float sm[];
    float* wl_s = sm;                     // [64*64]
    float* wr_s = sm + 4096;              // [64*64]
    float* a_s  = sm + 8192;              // [64][PAD]
    float* x_s  = sm + 8192 + NPB * PAD;  // [64][PAD]

    const int tid   = threadIdx.x;
    const int lane  = tid & 31;
    const int w     = tid >> 5;           // warp 0..31
    const int node0 = blockIdx.x * NPB;

    // stage weights (2048 float4, 2 per thread)
    for (int i = tid; i < DIM * DIM / 4; i += THR) {
        ((float4*)wl_s)[i] = ((const float4*)Wl)[i];
        ((float4*)wr_s)[i] = ((const float4*)Wr)[i];
    }
    // stage x rows: 64*16 = 1024 float4, 1 per thread
    {
        int i  = tid;
        int nl = i >> 4;          // node within block
        int kq = (i & 15) * 4;    // k offset
        int node = node0 + nl;
        if (node < N_NODES) {
            float4 v = *(const float4*)(x + node * DIM + kq);
            x_s[nl * PAD + kq + 0] = v.x;
            x_s[nl * PAD + kq + 1] = v.y;
            x_s[nl * PAD + kq + 2] = v.z;
            x_s[nl * PAD + kq + 3] = v.w;
        }
    }
    __syncthreads();

    // aggregation: warp w -> nodes w*2, w*2+1 (mean incl. self)
    const float2* xs = (const float2*)x;
    #pragma unroll 1
    for (int q = 0; q < 2; q++) {
        int nl = w * 2 + q;
        int n  = node0 + nl;
        if (n >= N_NODES) break;
        float a0 = x_s[nl * PAD + 2 * lane];
        float a1 = x_s[nl * PAD + 2 * lane + 1];
        int start = g_row[n];
        int cnt   = g_row[n + 1] - start;
        for (int base = 0; base < cnt; base += 32) {
            int rem = cnt - base;
            int m   = rem < 32 ? rem : 32;
            int c   = (lane < m) ? g_col[start + base + lane] : 0;
            int t = 0;
            for (; t + 4 <= m; t += 4) {
                int s0 = __shfl_sync(0xffffffffu, c, t);
                int s1 = __shfl_sync(0xffffffffu, c, t + 1);
                int s2 = __shfl_sync(0xffffffffu, c, t + 2);
                int s3 = __shfl_sync(0xffffffffu, c, t + 3);
                float2 v0 = xs[s0 * 32 + lane];
                float2 v1 = xs[s1 * 32 + lane];
                float2 v2 = xs[s2 * 32 + lane];
                float2 v3 = xs[s3 * 32 + lane];
                a0 += v0.x; a1 += v0.y;
                a0 += v1.x; a1 += v1.y;
                a0 += v2.x; a1 += v2.y;
                a0 += v3.x; a1 += v3.y;
            }
            for (; t < m; t++) {
                int s = __shfl_sync(0xffffffffu, c, t);
                float2 vv = xs[s * 32 + lane];
                a0 += vv.x; a1 += vv.y;
            }
        }
        float inv = 1.0f / (float)(cnt + 1);
        a_s[nl * PAD + 2 * lane]     = a0 * inv;
        a_s[nl * PAD + 2 * lane + 1] = a1 * inv;
    }
    __syncthreads();

    // GEMM: 1 node x 4 feats per thread (64 rows x 16 fcol-groups = 1024)
    const int nrow = tid >> 4;          // 0..63
    const int fc   = (tid & 15) << 2;   // 0,4,...,60

    float acc0 = 0.f, acc1 = 0.f, acc2 = 0.f, acc3 = 0.f;

    #pragma unroll 8
    for (int kk = 0; kk < DIM; kk++) {
        float4 wlv = *(const float4*)&wl_s[kk * DIM + fc];
        float4 wrv = *(const float4*)&wr_s[kk * DIM + fc];
        float av = a_s[nrow * PAD + kk];
        float xv = x_s[nrow * PAD + kk];
        acc0 += av * wlv.x + xv * wrv.x;
        acc1 += av * wlv.y + xv * wrv.y;
        acc2 += av * wlv.z + xv * wrv.z;
        acc3 += av * wlv.w + xv * wrv.w;
    }

    float4 bv = *(const float4*)(bl + fc);
    int node = node0 + nrow;
    if (node < N_NODES) {
        float4 o;
        o.x = fmaxf(acc0 + bv.x, 0.f);
        o.y = fmaxf(acc1 + bv.y, 0.f);
        o.z = fmaxf(acc2 + bv.z, 0.f);
        o.w = fmaxf(acc3 + bv.w, 0.f);
        *(float4*)(out + node * DIM + fc) = o;
    }
}

// ------------------------------------------------------------------ launch
extern "C" void kernel_launch(void* const* d_in, const int* in_sizes, int n_in,
                              void* d_out, int out_size) {
    const float* x   = (const float*)d_in[0];
    const int*   ei  = (const int*)  d_in[1];
    const float* Wl0 = (const float*)d_in[2];
    const float* bl0 = (const float*)d_in[3];
    const float* Wr0 = (const float*)d_in[4];
    const float* Wl1 = (const float*)d_in[5];
    const float* bl1 = (const float*)d_in[6];
    const float* Wr1 = (const float*)d_in[7];
    float* out = (float*)d_out;

    const int LAYER_SMEM = (8192 + 2 * NPB * PAD) * sizeof(float);  // 66048 B
    cudaFuncSetAttribute(k_layer, cudaFuncAttributeMaxDynamicSharedMemorySize,
                         LAYER_SMEM);

    int layer_blocks = (N_NODES + NPB - 1) / NPB;   // 782
    int edge4_blocks = (N_EDGES / 4 + 255) / 256;

    k_hist      <<<edge4_blocks, 256>>>(ei);                                   // 1
    k_scan_chain<<<NCHUNK, 1024>>>();                                          // 2
    k_scatter   <<<edge4_blocks, 256>>>(ei);                                   // 3
    k_layer     <<<layer_blocks, THR, LAYER_SMEM>>>(x,    Wl0, bl0, Wr0, g_x1); // 4 <- ncu
    k_layer     <<<layer_blocks, THR, LAYER_SMEM>>>(g_x1, Wl1, bl1, Wr1, out);  // 5
}

// round 17
// speedup vs baseline: 1.0001x; 1.0001x over previous
#include <cuda_runtime.h>

#define N_NODES 50000
#define N_EDGES 800000
#define DIM 64
#define NCHUNK 49            // ceil(50000/1024)
#define PAD 65               // smem row pitch (floats), conflict-free
#define NPB 64               // nodes per block
#define THR 1024             // threads per block (32 warps, 2 nodes/warp)

// Scratch (device globals — no allocation allowed). BSS zero-init at load.
__device__ int   g_deg[N_NODES];
__device__ int   g_row[N_NODES + 1];
__device__ int   g_cur[N_NODES];
__device__ int   g_col[N_EDGES];
__device__ float g_x1[N_NODES * DIM];
__device__ int   g_chain_val[NCHUNK];
__device__ int   g_chain_flag[NCHUNK];   // epoch counts, never reset

// ------------------------------------------------------------------ hist
__global__ void k_hist(const int* __restrict__ ei) {
    int t = blockIdx.x * blockDim.x + threadIdx.x;
    if (t < N_EDGES / 4) {
        int4 d = ((const int4*)(ei + N_EDGES))[t];
        atomicAdd(&g_deg[d.x], 1);
        atomicAdd(&g_deg[d.y], 1);
        atomicAdd(&g_deg[d.z], 1);
        atomicAdd(&g_deg[d.w], 1);
    }
}

// -------------------- chained exclusive scan (one kernel, 49 blocks) -----
__global__ void __launch_bounds__(1024) k_scan_chain() {
    __shared__ int wsum[32];
    __shared__ int s_base;
    int t = threadIdx.x, lane = t & 31, wid = t >> 5;
    int b = blockIdx.x;
    int i = b * 1024 + t;
    int v = 0;
    if (i < N_NODES) { v = g_deg[i]; g_deg[i] = 0; }
    int sc = v;
    #pragma unroll
    for (int off = 1; off < 32; off <<= 1) {
        int n = __shfl_up_sync(0xffffffffu, sc, off);
        if (lane >= off) sc += n;
    }
    if (lane == 31) wsum[wid] = sc;
    __syncthreads();
    if (wid == 0) {
        int w = wsum[lane];
        #pragma unroll
        for (int off = 1; off < 32; off <<= 1) {
            int n = __shfl_up_sync(0xffffffffu, w, off);
            if (lane >= off) w += n;
        }
        wsum[lane] = w;
    }
    __syncthreads();
    int wpre  = (wid > 0) ? wsum[wid - 1] : 0;
    int total = wsum[31];
    if (t == 0) {
        int E = g_chain_flag[b];
        int base = 0;
        if (b > 0) {
            while (atomicAdd(&g_chain_flag[b - 1], 0) <= E) {}
            __threadfence();
            base = g_chain_val[b - 1];
        }
        g_chain_val[b] = base + total;
        __threadfence();
        atomicExch(&g_chain_flag[b], E + 1);
        s_base = base;
    }
    __syncthreads();
    int ex = s_base + wpre + sc - v;
    if (i < N_NODES) { g_row[i] = ex; g_cur[i] = ex; }
    if (i == 0) g_row[N_NODES] = N_EDGES;
}

// --------------------------------------------------------------- scatter
__global__ void k_scatter(const int* __restrict__ ei) {
    int t = blockIdx.x * blockDim.x + threadIdx.x;
    if (t < N_EDGES / 4) {
        int4 s = ((const int4*)ei)[t];
        int4 d = ((const int4*)(ei + N_EDGES))[t];
        g_col[atomicAdd(&g_cur[d.x], 1)] = s.x;
        g_col[atomicAdd(&g_cur[d.y], 1)] = s.y;
        g_col[atomicAdd(&g_cur[d.z], 1)] = s.z;
        g_col[atomicAdd(&g_cur[d.w], 1)] = s.w;
    }
}

// ------------- fused layer: aggregation + GEMM + bias + relu --------------
// Block owns 64 nodes, 1024 threads = 32 warps (2 nodes per warp).
// Gather uses float4 loads with warp-halves: lanes 0-15 accumulate even-slot
// neighbors, lanes 16-31 odd-slot; each lane covers 4 feature columns.
// 2 neighbors per iteration at half the issue count of the float2 version.
__global__ void __launch_bounds__(THR, 2) k_layer(const float* __restrict__ x,
                                                  const float* __restrict__ Wl,
                                                  const float* __restrict__ bl,
                                                  const float* __restrict__ Wr,
                                                  float* __restrict__ out) {
    extern __shared__ float sm[];
    float* wl_s = sm;                     // [64*64]
    float* wr_s = sm + 4096;              // [64*64]
    float* a_s  = sm + 8192;              // [64][PAD]
    float* x_s  = sm + 8192 + NPB * PAD;  // [64][PAD]

    const int tid   = threadIdx.x;
    const int lane  = tid & 31;
    const int w     = tid >> 5;           // warp 0..31
    const int node0 = blockIdx.x * NPB;

    // stage weights (2048 float4, 2 per thread)
    for (int i = tid; i < DIM * DIM / 4; i += THR) {
        ((float4*)wl_s)[i] = ((const float4*)Wl)[i];
        ((float4*)wr_s)[i] = ((const float4*)Wr)[i];
    }
    // stage x rows: 64*16 = 1024 float4, 1 per thread
    {
        int i  = tid;
        int nl = i >> 4;          // node within block
        int kq = (i & 15) * 4;    // k offset
        int node = node0 + nl;
        if (node < N_NODES) {
            float4 v = *(const float4*)(x + node * DIM + kq);
            x_s[nl * PAD + kq + 0] = v.x;
            x_s[nl * PAD + kq + 1] = v.y;
            x_s[nl * PAD + kq + 2] = v.z;
            x_s[nl * PAD + kq + 3] = v.w;
        }
    }
    __syncthreads();

    // aggregation: warp w -> nodes w*2, w*2+1 (mean incl. self)
    const float4* x4 = (const float4*)x;
    const int half = lane >> 4;      // 0: even-slot neighbors, 1: odd-slot
    const int li   = lane & 15;      // covers feature cols 4*li..4*li+3
    #pragma unroll 1
    for (int q = 0; q < 2; q++) {
        int nl = w * 2 + q;
        int n  = node0 + nl;
        if (n >= N_NODES) break;
        float4 acc = make_float4(0.f, 0.f, 0.f, 0.f);
        int start = g_row[n];
        int cnt   = g_row[n + 1] - start;
        for (int base = 0; base < cnt; base += 32) {
            int rem = cnt - base;
            int m   = rem < 32 ? rem : 32;
            int c   = (lane < m) ? g_col[start + base + lane] : 0;
            for (int t = 0; t < m; t += 4) {
                int sA = t + half;          // < 32 always
                int sB = t + 2 + half;      // may exceed 31 -> mask; guarded by sB<m
                int iA = __shfl_sync(0xffffffffu, c, sA);
                int iB = __shfl_sync(0xffffffffu, c, sB & 31);
                float4 uA = x4[iA * 16 + li];
                float4 uB = x4[iB * 16 + li];
                if (sA < m) {
                    acc.x += uA.x; acc.y += uA.y; acc.z += uA.z; acc.w += uA.w;
                }
                if (sB < m) {
                    acc.x += uB.x; acc.y += uB.y; acc.z += uB.z; acc.w += uB.w;
                }
            }
        }
        // merge the two half-warp partial sums
        acc.x += __shfl_down_sync(0xffffffffu, acc.x, 16);
        acc.y += __shfl_down_sync(0xffffffffu, acc.y, 16);
        acc.z += __shfl_down_sync(0xffffffffu, acc.z, 16);
        acc.w += __shfl_down_sync(0xffffffffu, acc.w, 16);
        if (half == 0) {
            float inv = 1.0f / (float)(cnt + 1);
            int bo = nl * PAD + 4 * li;
            a_s[bo + 0] = (acc.x + x_s[bo + 0]) * inv;
            a_s[bo + 1] = (acc.y + x_s[bo + 1]) * inv;
            a_s[bo + 2] = (acc.z + x_s[bo + 2]) * inv;
            a_s[bo + 3] = (acc.w + x_s[bo + 3]) * inv;
        }
    }
    __syncthreads();

    // GEMM: 1 node x 4 feats per thread (64 rows x 16 fcol-groups = 1024)
    const int nrow = tid >> 4;          // 0..63
    const int fc   = (tid & 15) << 2;   // 0,4,...,60

    float acc0 = 0.f, acc1 = 0.f, acc2 = 0.f, acc3 = 0.f;

    #pragma unroll 8
    for (int kk = 0; kk < DIM; kk++) {
        float4 wlv = *(const float4*)&wl_s[kk * DIM + fc];
        float4 wrv = *(const float4*)&wr_s[kk * DIM + fc];
        float av = a_s[nrow * PAD + kk];
        float xv = x_s[nrow * PAD + kk];
        acc0 += av * wlv.x + xv * wrv.x;
        acc1 += av * wlv.y + xv * wrv.y;
        acc2 += av * wlv.z + xv * wrv.z;
        acc3 += av * wlv.w + xv * wrv.w;
    }

    float4 bv = *(const float4*)(bl + fc);
    int node = node0 + nrow;
    if (node < N_NODES) {
        float4 o;
        o.x = fmaxf(acc0 + bv.x, 0.f);
        o.y = fmaxf(acc1 + bv.y, 0.f);
        o.z = fmaxf(acc2 + bv.z, 0.f);
        o.w = fmaxf(acc3 + bv.w, 0.f);
        *(float4*)(out + node * DIM + fc) = o;
    }
}

// ------------------------------------------------------------------ launch
extern "C" void kernel_launch(void* const* d_in, const int* in_sizes, int n_in,
                              void* d_out, int out_size) {
    const float* x   = (const float*)d_in[0];
    const int*   ei  = (const int*)  d_in[1];
    const float* Wl0 = (const float*)d_in[2];
    const float* bl0 = (const float*)d_in[3];
    const float* Wr0 = (const float*)d_in[4];
    const float* Wl1 = (const float*)d_in[5];
    const float* bl1 = (const float*)d_in[6];
    const float* Wr1 = (const float*)d_in[7];
    float* out = (float*)d_out;

    const int LAYER_SMEM = (8192 + 2 * NPB * PAD) * sizeof(float);  // 66048 B
    cudaFuncSetAttribute(k_layer, cudaFuncAttributeMaxDynamicSharedMemorySize,
                         LAYER_SMEM);

    int layer_blocks = (N_NODES + NPB - 1) / NPB;   // 782
    int edge4_blocks = (N_EDGES / 4 + 255) / 256;

    k_hist      <<<edge4_blocks, 256>>>(ei);                                   // 1
    k_scan_chain<<<NCHUNK, 1024>>>();                                          // 2
    k_scatter   <<<edge4_blocks, 256>>>(ei);                                   // 3
    k_layer     <<<layer_blocks, THR, LAYER_SMEM>>>(x,    Wl0, bl0, Wr0, g_x1); // 4 <- ncu
    k_layer     <<<layer_blocks, THR, LAYER_SMEM>>>(g_x1, Wl1, bl1, Wr1, out);  // 5
}